// round 4
// baseline (speedup 1.0000x reference)
#include <cuda_runtime.h>
#include <cuda_bf16.h>
#include <stdint.h>

// Problem constants (fixed by the dataset)
#define N_NODES 50000
#define N_EDGES 800000
#define D 64
#define LN_EPS 1e-5f

// Scratch as float4 arrays: guarantees 16B alignment for 128-bit RED/LDG.
__device__ float4 g_xw4[N_NODES * (D / 4)];   // x @ W
__device__ float4 g_z4[N_NODES * (D / 4)];    // scattered messages
__device__ float g_deg[N_NODES];              // in-degree incl. self loop
__device__ float g_dinv[N_NODES];             // rsqrt(deg)

// Explicit global-space vector reduction (sm_90+). Avoids generic-space
// atom.add.v4.f32 which traps (err 717) on sm_103a.
__device__ __forceinline__ void red_global_add_v4(float4* addr, float4 v) {
    asm volatile("red.global.add.v4.f32 [%0], {%1, %2, %3, %4};"
                 :: "l"(addr), "f"(v.x), "f"(v.y), "f"(v.z), "f"(v.w)
                 : "memory");
}

// ---------------------------------------------------------------------------
// Kernel 1: xw = x @ W  (W cached in smem), plus init z=0, deg=1
// Block: 32 x 8 threads; each block handles 8 rows; lane handles 2 columns.
// ---------------------------------------------------------------------------
__global__ void gemm_init_kernel(const float* __restrict__ x,
                                 const float* __restrict__ W) {
    __shared__ float2 Ws[D * (D / 2)];   // W as float2 per row: [k][c2]
    int tid = threadIdx.y * 32 + threadIdx.x;
    const float2* W2 = reinterpret_cast<const float2*>(W);
    for (int i = tid; i < D * (D / 2); i += 256) Ws[i] = W2[i];
    __syncthreads();

    int row = blockIdx.x * 8 + threadIdx.y;
    if (row >= N_NODES) return;
    int lane = threadIdx.x;           // 0..31 -> columns 2*lane, 2*lane+1

    const float* xr = x + (size_t)row * D;
    float a0 = 0.f, a1 = 0.f;
#pragma unroll
    for (int k = 0; k < D; k++) {
        float xv = __ldg(xr + k);            // broadcast within warp
        float2 w = Ws[k * 32 + lane];
        a0 = fmaf(xv, w.x, a0);
        a1 = fmaf(xv, w.y, a1);
    }
    float2* xw2 = reinterpret_cast<float2*>(g_xw4);
    float2* z2  = reinterpret_cast<float2*>(g_z4);
    xw2[row * 32 + lane] = make_float2(a0, a1);
    z2[row * 32 + lane]  = make_float2(0.f, 0.f);   // init scatter target
    if (lane == 0) g_deg[row] = 1.0f;               // self-loop degree
}

// ---------------------------------------------------------------------------
// Kernel 2: degree count over edges (dst side)
// ---------------------------------------------------------------------------
__global__ void degree_kernel(const int* __restrict__ dst) {
    int e = blockIdx.x * blockDim.x + threadIdx.x;
    if (e < N_EDGES) {
        atomicAdd(&g_deg[dst[e]], 1.0f);
    }
}

// ---------------------------------------------------------------------------
// Kernel 3: dinv = rsqrt(deg)
// ---------------------------------------------------------------------------
__global__ void dinv_kernel() {
    int i = blockIdx.x * blockDim.x + threadIdx.x;
    if (i < N_NODES) {
        g_dinv[i] = rsqrtf(g_deg[i]);
    }
}

// ---------------------------------------------------------------------------
// Kernel 4: edge scatter  z[dst] += dinv[src]*dinv[dst] * xw[src]
// 16 threads per edge, each handles one float4 (16B), 128-bit global RED.
// ---------------------------------------------------------------------------
__global__ void scatter_kernel(const int* __restrict__ src,
                               const int* __restrict__ dst) {
    long long t = (long long)blockIdx.x * blockDim.x + threadIdx.x;
    int e = (int)(t >> 4);
    int c = (int)(t & 15);
    if (e >= N_EDGES) return;

    int s = src[e];
    int d = dst[e];
    float coef = g_dinv[s] * g_dinv[d];

    const float4* xs = g_xw4 + (size_t)s * 16;
    float4 v = __ldg(xs + c);
    float4 w = make_float4(v.x * coef, v.y * coef, v.z * coef, v.w * coef);

    red_global_add_v4(g_z4 + (size_t)d * 16 + c, w);
}

// ---------------------------------------------------------------------------
// Kernel 5: h = x + (z + dinv^2*xw + b); LayerNorm; ReLU. Warp per row.
// ---------------------------------------------------------------------------
__global__ void finalize_kernel(const float* __restrict__ x,
                                const float* __restrict__ b,
                                const float* __restrict__ gamma,
                                const float* __restrict__ beta,
                                float* __restrict__ out) {
    int warp = threadIdx.x >> 5;
    int lane = threadIdx.x & 31;
    int row = blockIdx.x * (blockDim.x >> 5) + warp;
    if (row >= N_NODES) return;

    float di = g_dinv[row];
    float sl = di * di;   // self-loop norm

    const float2* x2 = reinterpret_cast<const float2*>(x);
    const float2* xw2 = reinterpret_cast<const float2*>(g_xw4);
    const float2* z2 = reinterpret_cast<const float2*>(g_z4);
    const float2* b2 = reinterpret_cast<const float2*>(b);

    float2 xv = x2[(size_t)row * 32 + lane];
    float2 wv = xw2[(size_t)row * 32 + lane];
    float2 zv = z2[(size_t)row * 32 + lane];
    float2 bv = b2[lane];

    float h0 = xv.x + zv.x + sl * wv.x + bv.x;
    float h1 = xv.y + zv.y + sl * wv.y + bv.y;

    // warp reduce sum and sum of squares
    float s  = h0 + h1;
    float sq = h0 * h0 + h1 * h1;
#pragma unroll
    for (int off = 16; off > 0; off >>= 1) {
        s  += __shfl_xor_sync(0xFFFFFFFF, s,  off);
        sq += __shfl_xor_sync(0xFFFFFFFF, sq, off);
    }
    float mu  = s * (1.0f / D);
    float var = sq * (1.0f / D) - mu * mu;
    float rstd = rsqrtf(var + LN_EPS);

    const float2* g2 = reinterpret_cast<const float2*>(gamma);
    const float2* be2 = reinterpret_cast<const float2*>(beta);
    float2 gv = g2[lane];
    float2 bev = be2[lane];

    float o0 = (h0 - mu) * rstd * gv.x + bev.x;
    float o1 = (h1 - mu) * rstd * gv.y + bev.y;
    o0 = fmaxf(o0, 0.0f);
    o1 = fmaxf(o1, 0.0f);

    float2* out2 = reinterpret_cast<float2*>(out);
    out2[(size_t)row * 32 + lane] = make_float2(o0, o1);
}

// ---------------------------------------------------------------------------
extern "C" void kernel_launch(void* const* d_in, const int* in_sizes, int n_in,
                              void* d_out, int out_size) {
    const float* x = (const float*)d_in[0];
    const int* edge_index = (const int*)d_in[1];  // [2, E] int32 (JAX canonicalizes int64->int32)
    const float* W = (const float*)d_in[2];
    const float* b = (const float*)d_in[3];
    const float* gamma = (const float*)d_in[4];
    const float* beta = (const float*)d_in[5];
    float* out = (float*)d_out;

    const int* src = edge_index;            // edge_index[0]
    const int* dst = edge_index + N_EDGES;  // edge_index[1]

    // 1. GEMM + init (8 rows / block)
    {
        dim3 blk(32, 8);
        int grid = (N_NODES + 7) / 8;
        gemm_init_kernel<<<grid, blk>>>(x, W);
    }
    // 2. degree
    {
        int threads = 256;
        int grid = (N_EDGES + threads - 1) / threads;
        degree_kernel<<<grid, threads>>>(dst);
    }
    // 3. dinv
    {
        int threads = 256;
        int grid = (N_NODES + threads - 1) / threads;
        dinv_kernel<<<grid, threads>>>();
    }
    // 4. scatter (16 threads per edge)
    {
        long long total = (long long)N_EDGES * 16;
        int threads = 256;
        int grid = (int)((total + threads - 1) / threads);
        scatter_kernel<<<grid, threads>>>(src, dst);
    }
    // 5. finalize (warp per row, 8 warps per block)
    {
        int threads = 256;
        int grid = (N_NODES + 7) / 8;
        finalize_kernel<<<grid, threads>>>(x, b, gamma, beta, out);
    }
}

// round 5
// speedup vs baseline: 1.1450x; 1.1450x over previous
#include <cuda_runtime.h>
#include <cuda_bf16.h>
#include <stdint.h>

#define N_NODES 50000
#define N_EDGES 800000
#define D 64
#define LN_EPS 1e-5f
#define SCAN_BLK 256
#define N_SCAN_BLOCKS ((N_NODES + SCAN_BLK - 1) / SCAN_BLK)   // 196

// Scratch (static device globals; no allocation allowed)
__device__ float4 g_xw4[N_NODES * (D / 4)];   // x @ W (16B aligned)
__device__ float g_dinv[N_NODES];             // rsqrt(deg incl self-loop)
__device__ int   g_degi[N_NODES];             // edge in-degree (no self loop)
__device__ int   g_off[N_NODES + 1];          // CSR offsets
__device__ int   g_cursor[N_NODES];           // fill cursors
__device__ int   g_bsum[N_SCAN_BLOCKS];       // per-block degree sums
__device__ int   g_bpre[N_SCAN_BLOCKS];       // exclusive scan of block sums
__device__ int2  g_csr[N_EDGES];              // (src, coef-bits) per edge, by dst

// ---------------------------------------------------------------------------
// K1: xw = x @ W. x staged in smem (float4), W in smem. Also zero g_degi.
// Block 32x8: 8 rows/block, lane covers 2 cols (float2).
// ---------------------------------------------------------------------------
__global__ void gemm_init_kernel(const float* __restrict__ x,
                                 const float* __restrict__ W) {
    __shared__ float2 Ws[D * (D / 2)];     // W[k][c2]
    __shared__ float  Xs[8][D];            // 8 staged rows of x
    int tid = threadIdx.y * 32 + threadIdx.x;

    const float2* W2 = reinterpret_cast<const float2*>(W);
    for (int i = tid; i < D * (D / 2); i += 256) Ws[i] = W2[i];

    int row0 = blockIdx.x * 8;
    // cooperative float4 staging of 8 rows (8*16 = 128 float4)
    {
        const float4* x4 = reinterpret_cast<const float4*>(x);
        for (int i = tid; i < 8 * (D / 4); i += 256) {
            int r = i >> 4, c4 = i & 15;
            int row = row0 + r;
            float4 v = (row < N_NODES) ? x4[(size_t)row * 16 + c4]
                                       : make_float4(0.f, 0.f, 0.f, 0.f);
            reinterpret_cast<float4*>(&Xs[r][0])[c4] = v;
        }
    }
    __syncthreads();

    int row = row0 + threadIdx.y;
    if (row >= N_NODES) return;
    int lane = threadIdx.x;

    float a0 = 0.f, a1 = 0.f;
#pragma unroll
    for (int k = 0; k < D; k++) {
        float xv = Xs[threadIdx.y][k];         // smem broadcast
        float2 w = Ws[k * 32 + lane];
        a0 = fmaf(xv, w.x, a0);
        a1 = fmaf(xv, w.y, a1);
    }
    reinterpret_cast<float2*>(g_xw4)[(size_t)row * 32 + lane] = make_float2(a0, a1);
    if (lane == 0) g_degi[row] = 0;
}

// ---------------------------------------------------------------------------
// K2: edge in-degree histogram (dst side)
// ---------------------------------------------------------------------------
__global__ void degree_kernel(const int* __restrict__ dst) {
    int e = blockIdx.x * blockDim.x + threadIdx.x;
    if (e < N_EDGES) atomicAdd(&g_degi[dst[e]], 1);
}

// ---------------------------------------------------------------------------
// K3a: per-block exclusive scan of degrees; block sums to g_bsum
// ---------------------------------------------------------------------------
__global__ void scan_block_kernel() {
    __shared__ int sh[SCAN_BLK];
    int tid = threadIdx.x;
    int i = blockIdx.x * SCAN_BLK + tid;
    int val = (i < N_NODES) ? g_degi[i] : 0;
    sh[tid] = val;
    __syncthreads();
#pragma unroll
    for (int o = 1; o < SCAN_BLK; o <<= 1) {
        int t = (tid >= o) ? sh[tid - o] : 0;
        __syncthreads();
        sh[tid] += t;
        __syncthreads();
    }
    if (i < N_NODES) g_off[i] = sh[tid] - val;         // exclusive (block-local)
    if (tid == SCAN_BLK - 1) g_bsum[blockIdx.x] = sh[tid];
}

// ---------------------------------------------------------------------------
// K3b: scan block sums (single block), set g_off[N]
// ---------------------------------------------------------------------------
__global__ void scan_top_kernel() {
    __shared__ int sh[SCAN_BLK];
    int tid = threadIdx.x;
    int val = (tid < N_SCAN_BLOCKS) ? g_bsum[tid] : 0;
    sh[tid] = val;
    __syncthreads();
#pragma unroll
    for (int o = 1; o < SCAN_BLK; o <<= 1) {
        int t = (tid >= o) ? sh[tid - o] : 0;
        __syncthreads();
        sh[tid] += t;
        __syncthreads();
    }
    if (tid < N_SCAN_BLOCKS) g_bpre[tid] = sh[tid] - val;
    if (tid == 0) g_off[N_NODES] = N_EDGES;
}

// ---------------------------------------------------------------------------
// K3c: finalize offsets, init cursors, compute dinv = rsqrt(1 + deg)
// ---------------------------------------------------------------------------
__global__ void scan_fix_kernel() {
    int i = blockIdx.x * blockDim.x + threadIdx.x;
    if (i >= N_NODES) return;
    int off = g_off[i] + g_bpre[i / SCAN_BLK];
    g_off[i] = off;
    g_cursor[i] = off;
    g_dinv[i] = rsqrtf(1.0f + (float)g_degi[i]);
}

// ---------------------------------------------------------------------------
// K4: fill CSR: (src, coef) grouped by dst
// ---------------------------------------------------------------------------
__global__ void csr_fill_kernel(const int* __restrict__ src,
                                const int* __restrict__ dst) {
    int e = blockIdx.x * blockDim.x + threadIdx.x;
    if (e >= N_EDGES) return;
    int s = src[e];
    int d = dst[e];
    float coef = g_dinv[s] * g_dinv[d];
    int pos = atomicAdd(&g_cursor[d], 1);
    g_csr[pos] = make_int2(s, __float_as_int(coef));
}

// ---------------------------------------------------------------------------
// K5: fused gather + self-loop + skip + bias + LayerNorm + ReLU.
// Warp per node; lane covers 2 columns.
// ---------------------------------------------------------------------------
__global__ void gather_finalize_kernel(const float* __restrict__ x,
                                       const float* __restrict__ b,
                                       const float* __restrict__ gamma,
                                       const float* __restrict__ beta,
                                       float* __restrict__ out) {
    int warp = threadIdx.x >> 5;
    int lane = threadIdx.x & 31;
    int row = blockIdx.x * (blockDim.x >> 5) + warp;
    if (row >= N_NODES) return;

    int off0 = g_off[row];
    int off1 = g_off[row + 1];

    const float2* xw2 = reinterpret_cast<const float2*>(g_xw4);

    float z0 = 0.f, z1 = 0.f;
    for (int k = off0; k < off1; k++) {
        int2 sc = __ldg(&g_csr[k]);                 // broadcast within warp
        float c = __int_as_float(sc.y);
        float2 v = xw2[(size_t)sc.x * 32 + lane];   // 256B/warp gather (L2)
        z0 = fmaf(c, v.x, z0);
        z1 = fmaf(c, v.y, z1);
    }

    float di = g_dinv[row];
    float sl = di * di;                              // self-loop coefficient

    const float2* x2 = reinterpret_cast<const float2*>(x);
    float2 xv = x2[(size_t)row * 32 + lane];
    float2 wv = xw2[(size_t)row * 32 + lane];
    float2 bv = reinterpret_cast<const float2*>(b)[lane];

    float h0 = xv.x + z0 + sl * wv.x + bv.x;
    float h1 = xv.y + z1 + sl * wv.y + bv.y;

    float s = h0 + h1;
    float sq = h0 * h0 + h1 * h1;
#pragma unroll
    for (int o = 16; o > 0; o >>= 1) {
        s  += __shfl_xor_sync(0xFFFFFFFF, s,  o);
        sq += __shfl_xor_sync(0xFFFFFFFF, sq, o);
    }
    float mu = s * (1.0f / D);
    float var = sq * (1.0f / D) - mu * mu;
    float rstd = rsqrtf(var + LN_EPS);

    float2 gv  = reinterpret_cast<const float2*>(gamma)[lane];
    float2 bev = reinterpret_cast<const float2*>(beta)[lane];

    float o0 = fmaxf((h0 - mu) * rstd * gv.x + bev.x, 0.f);
    float o1 = fmaxf((h1 - mu) * rstd * gv.y + bev.y, 0.f);

    reinterpret_cast<float2*>(out)[(size_t)row * 32 + lane] = make_float2(o0, o1);
}

// ---------------------------------------------------------------------------
extern "C" void kernel_launch(void* const* d_in, const int* in_sizes, int n_in,
                              void* d_out, int out_size) {
    const float* x = (const float*)d_in[0];
    const int* edge_index = (const int*)d_in[1];   // [2, E] int32
    const float* W = (const float*)d_in[2];
    const float* b = (const float*)d_in[3];
    const float* gamma = (const float*)d_in[4];
    const float* beta = (const float*)d_in[5];
    float* out = (float*)d_out;

    const int* src = edge_index;
    const int* dst = edge_index + N_EDGES;

    // K1: GEMM + degi init
    {
        dim3 blk(32, 8);
        gemm_init_kernel<<<(N_NODES + 7) / 8, blk>>>(x, W);
    }
    // K2: degree histogram
    degree_kernel<<<(N_EDGES + 255) / 256, 256>>>(dst);
    // K3: two-level scan + dinv
    scan_block_kernel<<<N_SCAN_BLOCKS, SCAN_BLK>>>();
    scan_top_kernel<<<1, SCAN_BLK>>>();
    scan_fix_kernel<<<(N_NODES + 255) / 256, 256>>>();
    // K4: CSR fill
    csr_fill_kernel<<<(N_EDGES + 255) / 256, 256>>>(src, dst);
    // K5: fused gather + LN + ReLU
    gather_finalize_kernel<<<(N_NODES + 7) / 8, 256>>>(x, b, gamma, beta, out);
}

// round 6
// speedup vs baseline: 1.1987x; 1.0469x over previous
#include <cuda_runtime.h>
#include <cuda_bf16.h>
#include <stdint.h>

#define N_NODES 50000
#define N_EDGES 800000
#define D 64
#define LN_EPS 1e-5f
#define SCAN_BLK 256
#define N_SCAN_BLOCKS ((N_NODES + SCAN_BLK - 1) / SCAN_BLK)   // 196
#define GEMM_BLOCKS ((N_NODES + 7) / 8)                       // 6250
#define HIST_T (N_EDGES / 4)                                  // 200000 int4 loads
#define HIST_BLOCKS ((HIST_T + 255) / 256)                    // 782

// Scratch (static device globals; zero-initialized at module load)
__device__ float4 g_xw4[N_NODES * (D / 4)];   // x @ W (16B aligned)
__device__ float g_dinv[N_NODES];             // rsqrt(1 + deg)
__device__ int   g_degi[N_NODES];             // edge in-degree (maintained zero between calls)
__device__ int   g_loc[N_NODES];              // block-local exclusive scan of degrees
__device__ int   g_cursor[N_NODES];           // per-node fill cursor (starts 0)
__device__ int   g_bsum[N_SCAN_BLOCKS];       // per-block degree sums
__device__ int   g_bpre[N_SCAN_BLOCKS];       // exclusive scan of block sums
__device__ int   g_csr_src[N_EDGES];          // src index per edge, grouped by dst

// ---------------------------------------------------------------------------
// K1: fused  (a) xw = x @ W   (b) in-degree histogram.
// Blocks [0, GEMM_BLOCKS): gemm, 8 rows/block (32x8 threads).
// Blocks [GEMM_BLOCKS, ...): histogram, 4 edges/thread via int4.
// g_degi enters zeroed (static init on call 1; gather re-zeroes afterwards).
// ---------------------------------------------------------------------------
__global__ void fused_gemm_hist_kernel(const float* __restrict__ x,
                                       const float* __restrict__ W,
                                       const int* __restrict__ dst) {
    if (blockIdx.x >= GEMM_BLOCKS) {
        // -------- histogram part --------
        int t = (blockIdx.x - GEMM_BLOCKS) * 256 + (threadIdx.y * 32 + threadIdx.x);
        if (t < HIST_T) {
            int4 d4 = __ldg(reinterpret_cast<const int4*>(dst) + t);
            atomicAdd(&g_degi[d4.x], 1);
            atomicAdd(&g_degi[d4.y], 1);
            atomicAdd(&g_degi[d4.z], 1);
            atomicAdd(&g_degi[d4.w], 1);
        }
        return;
    }
    // -------- gemm part --------
    __shared__ float2 Ws[D * (D / 2)];     // W[k][c2]
    __shared__ float  Xs[8][D];            // 8 staged rows of x
    int tid = threadIdx.y * 32 + threadIdx.x;

    const float2* W2 = reinterpret_cast<const float2*>(W);
    for (int i = tid; i < D * (D / 2); i += 256) Ws[i] = W2[i];

    int row0 = blockIdx.x * 8;
    {
        const float4* x4 = reinterpret_cast<const float4*>(x);
        for (int i = tid; i < 8 * (D / 4); i += 256) {
            int r = i >> 4, c4 = i & 15;
            int row = row0 + r;
            float4 v = (row < N_NODES) ? x4[(size_t)row * 16 + c4]
                                       : make_float4(0.f, 0.f, 0.f, 0.f);
            reinterpret_cast<float4*>(&Xs[r][0])[c4] = v;
        }
    }
    __syncthreads();

    int row = row0 + threadIdx.y;
    if (row >= N_NODES) return;
    int lane = threadIdx.x;

    float a0 = 0.f, a1 = 0.f;
#pragma unroll
    for (int k = 0; k < D; k++) {
        float xv = Xs[threadIdx.y][k];         // smem broadcast
        float2 w = Ws[k * 32 + lane];
        a0 = fmaf(xv, w.x, a0);
        a1 = fmaf(xv, w.y, a1);
    }
    reinterpret_cast<float2*>(g_xw4)[(size_t)row * 32 + lane] = make_float2(a0, a1);
}

// ---------------------------------------------------------------------------
// K2: block-local exclusive scan of degrees; block sums; dinv; cursor=0.
// ---------------------------------------------------------------------------
__global__ void scan_block_kernel() {
    __shared__ int sh[SCAN_BLK];
    int tid = threadIdx.x;
    int i = blockIdx.x * SCAN_BLK + tid;
    int val = (i < N_NODES) ? g_degi[i] : 0;
    sh[tid] = val;
    __syncthreads();
#pragma unroll
    for (int o = 1; o < SCAN_BLK; o <<= 1) {
        int t = (tid >= o) ? sh[tid - o] : 0;
        __syncthreads();
        sh[tid] += t;
        __syncthreads();
    }
    if (i < N_NODES) {
        g_loc[i] = sh[tid] - val;              // block-local exclusive
        g_cursor[i] = 0;
        g_dinv[i] = rsqrtf(1.0f + (float)val); // self-loop included
    }
    if (tid == SCAN_BLK - 1) g_bsum[blockIdx.x] = sh[tid];
}

// ---------------------------------------------------------------------------
// K3: single-warp shfl scan of the 196 block sums -> g_bpre (exclusive).
// ---------------------------------------------------------------------------
__global__ void scan_top_kernel() {
    const int CH = 7;                        // 32*7 = 224 >= 196
    int lane = threadIdx.x;                  // launched with 32 threads
    int base = lane * CH;
    int v[CH];
    int sum = 0;
#pragma unroll
    for (int j = 0; j < CH; j++) {
        int idx = base + j;
        v[j] = (idx < N_SCAN_BLOCKS) ? g_bsum[idx] : 0;
        sum += v[j];
    }
    int pre = sum;
#pragma unroll
    for (int o = 1; o < 32; o <<= 1) {
        int t = __shfl_up_sync(0xFFFFFFFF, pre, o);
        if (lane >= o) pre += t;
    }
    pre -= sum;                              // exclusive prefix of chunk
    int run = pre;
#pragma unroll
    for (int j = 0; j < CH; j++) {
        int idx = base + j;
        if (idx < N_SCAN_BLOCKS) g_bpre[idx] = run;
        run += v[j];
    }
}

// ---------------------------------------------------------------------------
// K4: CSR fill (src only). 4 edges/thread via int4.
// pos = loc[d] + bpre[d/256] + cursor[d]++
// ---------------------------------------------------------------------------
__global__ void csr_fill_kernel(const int* __restrict__ src,
                                const int* __restrict__ dst) {
    int t = blockIdx.x * blockDim.x + threadIdx.x;
    if (t >= HIST_T) return;
    int4 s4 = __ldg(reinterpret_cast<const int4*>(src) + t);
    int4 d4 = __ldg(reinterpret_cast<const int4*>(dst) + t);
#pragma unroll
    for (int j = 0; j < 4; j++) {
        int s = (j == 0) ? s4.x : (j == 1) ? s4.y : (j == 2) ? s4.z : s4.w;
        int d = (j == 0) ? d4.x : (j == 1) ? d4.y : (j == 2) ? d4.z : d4.w;
        int pos = g_loc[d] + g_bpre[d >> 8] + atomicAdd(&g_cursor[d], 1);
        g_csr_src[pos] = s;
    }
}

// ---------------------------------------------------------------------------
// K5: fused gather + self-loop + skip + bias + LayerNorm + ReLU.
// Warp per node; lane covers 2 columns. Re-zeroes g_degi for the next call.
// ---------------------------------------------------------------------------
__global__ void gather_finalize_kernel(const float* __restrict__ x,
                                       const float* __restrict__ b,
                                       const float* __restrict__ gamma,
                                       const float* __restrict__ beta,
                                       float* __restrict__ out) {
    int warp = threadIdx.x >> 5;
    int lane = threadIdx.x & 31;
    int row = blockIdx.x * (blockDim.x >> 5) + warp;
    if (row >= N_NODES) return;

    int off0 = g_loc[row] + g_bpre[row >> 8];
    int off1 = (row + 1 < N_NODES) ? (g_loc[row + 1] + g_bpre[(row + 1) >> 8])
                                   : N_EDGES;

    float dr = g_dinv[row];
    const float2* xw2 = reinterpret_cast<const float2*>(g_xw4);

    float z0 = 0.f, z1 = 0.f;
    for (int k = off0; k < off1; k++) {
        int s = __ldg(&g_csr_src[k]);               // warp-broadcast
        float c = __ldg(&g_dinv[s]) * dr;           // warp-broadcast
        float2 v = xw2[(size_t)s * 32 + lane];      // 256B/warp L2 gather
        z0 = fmaf(c, v.x, z0);
        z1 = fmaf(c, v.y, z1);
    }

    float sl = dr * dr;                              // self-loop coefficient

    float2 xv = reinterpret_cast<const float2*>(x)[(size_t)row * 32 + lane];
    float2 wv = xw2[(size_t)row * 32 + lane];
    float2 bv = reinterpret_cast<const float2*>(b)[lane];

    float h0 = xv.x + z0 + sl * wv.x + bv.x;
    float h1 = xv.y + z1 + sl * wv.y + bv.y;

    float s = h0 + h1;
    float sq = h0 * h0 + h1 * h1;
#pragma unroll
    for (int o = 16; o > 0; o >>= 1) {
        s  += __shfl_xor_sync(0xFFFFFFFF, s,  o);
        sq += __shfl_xor_sync(0xFFFFFFFF, sq, o);
    }
    float mu = s * (1.0f / D);
    float var = sq * (1.0f / D) - mu * mu;
    float rstd = rsqrtf(var + LN_EPS);

    float2 gv  = reinterpret_cast<const float2*>(gamma)[lane];
    float2 bev = reinterpret_cast<const float2*>(beta)[lane];

    float o0 = fmaxf((h0 - mu) * rstd * gv.x + bev.x, 0.f);
    float o1 = fmaxf((h1 - mu) * rstd * gv.y + bev.y, 0.f);

    reinterpret_cast<float2*>(out)[(size_t)row * 32 + lane] = make_float2(o0, o1);

    if (lane == 0) g_degi[row] = 0;   // restore invariant for next call
}

// ---------------------------------------------------------------------------
extern "C" void kernel_launch(void* const* d_in, const int* in_sizes, int n_in,
                              void* d_out, int out_size) {
    const float* x = (const float*)d_in[0];
    const int* edge_index = (const int*)d_in[1];   // [2, E] int32
    const float* W = (const float*)d_in[2];
    const float* b = (const float*)d_in[3];
    const float* gamma = (const float*)d_in[4];
    const float* beta = (const float*)d_in[5];
    float* out = (float*)d_out;

    const int* src = edge_index;
    const int* dst = edge_index + N_EDGES;

    // K1: fused GEMM + degree histogram
    {
        dim3 blk(32, 8);
        fused_gemm_hist_kernel<<<GEMM_BLOCKS + HIST_BLOCKS, blk>>>(x, W, dst);
    }
    // K2: block scan + dinv + cursor init
    scan_block_kernel<<<N_SCAN_BLOCKS, SCAN_BLK>>>();
    // K3: top scan (1 warp)
    scan_top_kernel<<<1, 32>>>();
    // K4: CSR fill
    csr_fill_kernel<<<(HIST_T + 255) / 256, 256>>>(src, dst);
    // K5: fused gather + LN + ReLU (+ degi re-zero)
    gather_finalize_kernel<<<(N_NODES + 7) / 8, 256>>>(x, b, gamma, beta, out);
}